// round 4
// baseline (speedup 1.0000x reference)
#include <cuda_runtime.h>
#include <math.h>

#define BATCH   512
#define STEPS   128
#define TSTEPS  255          // 127 history + 128 action
#define DIN     256
#define UDIM    256
#define G4      1024         // 4*UDIM

// Cluster recurrence geometry
#define CLSZ    8            // CTAs per cluster (feature split 256/8 = 32)
#define NCLUST  16           // clusters (rows split 512/16 = 32)
#define CROWS   32           // batch rows per cluster
#define NFEAT   32           // gate features per CTA
#define RTHREADS 512         // 32 features x 16 row-groups (2 rows each)
#define WS_BYTES (256 * NFEAT * 16)          // 128 KB weight slice
#define HS_BYTES (CROWS * 256 * 8)           // 64 KB duplicated h
#define RSMEM    (WS_BYTES + HS_BYTES)       // 192 KB

// Scratch (static device allocations — no cudaMalloc anywhere)
__device__ float  g_state[BATCH * UDIM];
__device__ float  g_h[BATCH * UDIM];
__device__ float  g_G[(size_t)TSTEPS * BATCH * G4];   // 535 MB: x@Wk + bl, [t][b][4U]
__device__ float4 g_W4[256 * 256];                    // Wrk reformat: (wi,wf,wg,wo) per (k,n)

// ---------------------------------------------------------------------------
// f32x2 packed-FMA helpers (sm_103a FFMA2 — only reachable via PTX)
// ---------------------------------------------------------------------------
union F2U { float2 f; unsigned long long u; };
union F4U { float4 f; ulonglong2 u; };

__device__ __forceinline__ void fma2(unsigned long long& d,
                                     unsigned long long a,
                                     unsigned long long b)
{
    asm("fma.rn.f32x2 %0, %1, %2, %0;" : "+l"(d) : "l"(a), "l"(b));
}
__device__ __forceinline__ unsigned long long dup2(float x)
{
    F2U t; t.f = make_float2(x, x); return t.u;
}
__device__ __forceinline__ float tanha(float x)
{
    float y; asm("tanh.approx.f32 %0, %1;" : "=f"(y) : "f"(x)); return y;
}
__device__ __forceinline__ float sigm(float x)
{
    return fmaf(0.5f, tanha(0.5f * x), 0.5f);
}

// ---------------------------------------------------------------------------
// K0: reformat Wrk [256,1024] -> W4[k][n] = (W[k][n], W[k][256+n], W[k][512+n], W[k][768+n])
// ---------------------------------------------------------------------------
__global__ void reformat_wrk(const float* __restrict__ Wrk)
{
    const int idx = blockIdx.x * 256 + threadIdx.x;   // 65536
    const int k = idx >> 8, n = idx & 255;
    const float* w = Wrk + k * G4 + n;
    g_W4[idx] = make_float4(w[0], w[256], w[512], w[768]);
}

// ---------------------------------------------------------------------------
// K1: preamble — ms/rs/re/im + combine -> state [512,256]
// ---------------------------------------------------------------------------
__global__ void __launch_bounds__(256) preamble_kernel(
    const float* __restrict__ motion, const float* __restrict__ robot,
    const float* __restrict__ osr,    const float* __restrict__ osi,
    const float* __restrict__ orr_,   const float* __restrict__ ori_,
    const float* __restrict__ Wm, const float* __restrict__ bm,
    const float* __restrict__ Wr, const float* __restrict__ br,
    const float* __restrict__ Wre, const float* __restrict__ bre,
    const float* __restrict__ Wim, const float* __restrict__ bim,
    const float* __restrict__ Wc,  const float* __restrict__ bc)
{
    __shared__ float comb[768];
    const int row = blockIdx.x;
    const int n   = threadIdx.x;

    float s = bm[n];
    #pragma unroll 8
    for (int k = 0; k < 64; k++) s += motion[row*64 + k] * Wm[k*256 + n];
    comb[n] = fmaxf(s, 0.f);

    s = br[n];
    #pragma unroll 8
    for (int k = 0; k < 128; k++) s += robot[row*128 + k] * Wr[k*256 + n];
    comb[256 + n] = fmaxf(s, 0.f);

    if (n < 128) {
        float s3 = bre[n];
        #pragma unroll 8
        for (int k = 0; k < 64; k++) s3 += osr [row*64 + k] * Wre[k*128 + n];
        #pragma unroll 8
        for (int k = 0; k < 64; k++) s3 += orr_[row*64 + k] * Wre[(64+k)*128 + n];
        comb[512 + n] = fmaxf(s3, 0.f);
    } else {
        const int m = n - 128;
        float s4 = bim[m];
        #pragma unroll 8
        for (int k = 0; k < 64; k++) s4 += osi [row*64 + k] * Wim[k*128 + m];
        #pragma unroll 8
        for (int k = 0; k < 64; k++) s4 += ori_[row*64 + k] * Wim[(64+k)*128 + m];
        comb[640 + m] = fmaxf(s4, 0.f);
    }
    __syncthreads();

    float s5 = bc[n];
    #pragma unroll 8
    for (int k = 0; k < 768; k++) s5 += comb[k] * Wc[k*256 + n];
    g_state[row*256 + n] = fmaxf(s5, 0.f);
}

// ---------------------------------------------------------------------------
// K2: G = x @ Wk + bl.  M=130560, K=256, N=1024.
// 128x128 tile, BK=16, 256 threads, 8x8 microtile, FFMA2, reg-prefetch.
// ---------------------------------------------------------------------------
__global__ void __launch_bounds__(256, 1) xwk_kernel(
    const float* __restrict__ hist, const float* __restrict__ act,
    const float* __restrict__ Wk,   const float* __restrict__ bl)
{
    __shared__ float As[16][132];   // [k][m], padded
    __shared__ float Bs[16][128];   // [k][n]

    const int tid = threadIdx.x;
    const int tx  = tid & 15, ty = tid >> 4;
    const int bm0 = blockIdx.y * 128;
    const int bn0 = blockIdx.x * 128;

    const int ra = tid >> 2;              // 0..63
    const int kc = (tid & 3) * 4;         // 0,4,8,12
    const int mA0 = bm0 + ra, mA1 = bm0 + ra + 64;
    const int tA0 = mA0 >> 9, bA0 = mA0 & 511;
    const int tA1 = mA1 >> 9, bA1 = mA1 & 511;
    const float* arow0 = (tA0 < 127)
        ? (hist + ((size_t)bA0 * STEPS + tA0) * DIN)
        : (act  + ((size_t)bA0 * STEPS + (tA0 - 127)) * DIN);
    const float* arow1 = (tA1 < 127)
        ? (hist + ((size_t)bA1 * STEPS + tA1) * DIN)
        : (act  + ((size_t)bA1 * STEPS + (tA1 - 127)) * DIN);

    const int kb = tid >> 4;              // 0..15
    const int nb = (tid & 15) * 4;        // 0..60
    const float* bsrc = Wk + (size_t)kb * G4 + bn0 + nb;

    unsigned long long acc[8][4];
    #pragma unroll
    for (int i = 0; i < 8; i++)
        #pragma unroll
        for (int j = 0; j < 4; j++) acc[i][j] = 0ull;

    float4 a0 = *(const float4*)(arow0 + kc);
    float4 a1 = *(const float4*)(arow1 + kc);
    float4 b0 = *(const float4*)(bsrc);
    float4 b1 = *(const float4*)(bsrc + 64);

    for (int k0 = 0; k0 < 256; k0 += 16) {
        __syncthreads();
        As[kc+0][ra] = a0.x; As[kc+1][ra] = a0.y; As[kc+2][ra] = a0.z; As[kc+3][ra] = a0.w;
        As[kc+0][ra+64] = a1.x; As[kc+1][ra+64] = a1.y; As[kc+2][ra+64] = a1.z; As[kc+3][ra+64] = a1.w;
        *(float4*)&Bs[kb][nb]      = b0;
        *(float4*)&Bs[kb][nb + 64] = b1;
        __syncthreads();

        if (k0 + 16 < 256) {
            a0 = *(const float4*)(arow0 + k0 + 16 + kc);
            a1 = *(const float4*)(arow1 + k0 + 16 + kc);
            b0 = *(const float4*)(bsrc + (size_t)(k0 + 16) * G4);
            b1 = *(const float4*)(bsrc + (size_t)(k0 + 16) * G4 + 64);
        }

        #pragma unroll
        for (int k = 0; k < 16; k++) {
            float4 av0 = *(const float4*)&As[k][ty*8];
            float4 av1 = *(const float4*)&As[k][ty*8 + 4];
            F4U bv0, bv1;
            bv0.f = *(const float4*)&Bs[k][tx*8];
            bv1.f = *(const float4*)&Bs[k][tx*8 + 4];
            unsigned long long bp[4] = { bv0.u.x, bv0.u.y, bv1.u.x, bv1.u.y };
            float afl[8] = { av0.x, av0.y, av0.z, av0.w, av1.x, av1.y, av1.z, av1.w };
            #pragma unroll
            for (int i = 0; i < 8; i++) {
                unsigned long long ad = dup2(afl[i]);
                #pragma unroll
                for (int j = 0; j < 4; j++) fma2(acc[i][j], ad, bp[j]);
            }
        }
    }

    float blv[8];
    #pragma unroll
    for (int j = 0; j < 8; j++) blv[j] = bl[bn0 + tx*8 + j];

    #pragma unroll
    for (int i = 0; i < 8; i++) {
        const int m = bm0 + ty*8 + i;
        float v[8];
        #pragma unroll
        for (int j = 0; j < 4; j++) {
            F2U e; e.u = acc[i][j];
            v[j*2]   = e.f.x + blv[j*2];
            v[j*2+1] = e.f.y + blv[j*2+1];
        }
        float* dst = g_G + (size_t)m * G4 + bn0 + tx*8;
        *(float4*)dst       = make_float4(v[0], v[1], v[2], v[3]);
        *(float4*)(dst + 4) = make_float4(v[4], v[5], v[6], v[7]);
    }
}

// ---------------------------------------------------------------------------
// K3: cluster-feature-split LSTM recurrence.
// 16 clusters x 8 CTAs. Cluster owns 32 batch rows; CTA owns 32 gate features.
// Weight slice (128 KB) loaded into smem ONCE, reused all 255 steps.
// h exchanged per step via g_h (L2) + barrier.cluster (release/acquire at
// cluster scope -> CCTL.IVALL, so plain LDG after the barrier is coherent).
// Thread (n', rg): 2 rows x 1 feature, full K=256 dot products (no k-split).
// ---------------------------------------------------------------------------
__global__ void __launch_bounds__(RTHREADS, 1) __cluster_dims__(CLSZ, 1, 1)
recur_cluster_kernel()
{
    extern __shared__ char smem[];
    float4* ws = (float4*)smem;                       // [k=256][n'=32] float4
    float2* hs = (float2*)(smem + WS_BYTES);          // [r=32][k=256] dup'd h

    const int tid = threadIdx.x;
    const int np  = tid & 31;                         // feature within CTA
    const int rg  = tid >> 5;                         // row group 0..15 (== warp id)
    const int rank = blockIdx.x & (CLSZ - 1);         // cluster CTA rank
    const int cid  = blockIdx.x >> 3;                 // cluster id
    const int n0   = rank * NFEAT;                    // global feature base
    const int row0 = cid * CROWS;                     // global row base
    const int ra   = row0 + 2 * rg;                   // this thread's row pair

    // One-time: load weight slice into smem.  Warp w loads k rows [16w,16w+16).
    {
        const int wbase = rg * 16;
        #pragma unroll
        for (int kk = 0; kk < 16; kk++) {
            const int k = wbase + kk;
            ws[k * NFEAT + np] = g_W4[k * 256 + n0 + np];
        }
    }
    // One-time: h(0) = state, duplicated.
    for (int idx = tid; idx < CROWS * 256; idx += RTHREADS) {
        const float v = g_state[(row0 + (idx >> 8)) * 256 + (idx & 255)];
        hs[idx] = make_float2(v, v);
    }
    float c0 = g_state[ra * 256 + n0 + np];
    float c1 = g_state[(ra + 1) * 256 + n0 + np];
    __syncthreads();

    const float2* h0p = hs + (2 * rg) * 256;
    const float2* h1p = hs + (2 * rg + 1) * 256;
    const float4* wp  = ws + np;

    for (int t = 0; t < TSTEPS; t++) {
        // Prefetch G for this step (lands under the k-loop)
        const float* Gp0 = g_G + ((size_t)t * BATCH + ra) * G4 + n0 + np;
        const float* Gp1 = Gp0 + G4;
        const float gi0 = Gp0[0], gf0 = Gp0[256], gg0 = Gp0[512], go0 = Gp0[768];
        const float gi1 = Gp1[0], gf1 = Gp1[256], gg1 = Gp1[512], go1 = Gp1[768];

        unsigned long long aif0a = 0, aif0b = 0, ago0a = 0, ago0b = 0;
        unsigned long long aif1a = 0, aif1b = 0, ago1a = 0, ago1b = 0;

        #pragma unroll 8
        for (int k2 = 0; k2 < 128; k2++) {
            F4U w0, w1, h0, h1;
            w0.f = wp[(2 * k2) * NFEAT];
            w1.f = wp[(2 * k2 + 1) * NFEAT];
            h0.f = *(const float4*)(h0p + 2 * k2);    // (h_k,h_k,h_k1,h_k1) row0
            h1.f = *(const float4*)(h1p + 2 * k2);    // row1
            fma2(aif0a, w0.u.x, h0.u.x); fma2(ago0a, w0.u.y, h0.u.x);
            fma2(aif0b, w1.u.x, h0.u.y); fma2(ago0b, w1.u.y, h0.u.y);
            fma2(aif1a, w0.u.x, h1.u.x); fma2(ago1a, w0.u.y, h1.u.x);
            fma2(aif1b, w1.u.x, h1.u.y); fma2(ago1b, w1.u.y, h1.u.y);
        }

        F2U e0, e1, e2, e3, e4, e5, e6, e7;
        e0.u = aif0a; e1.u = aif0b; e2.u = ago0a; e3.u = ago0b;
        e4.u = aif1a; e5.u = aif1b; e6.u = ago1a; e7.u = ago1b;

        const float zi0 = e0.f.x + e1.f.x + gi0;
        const float zf0 = e0.f.y + e1.f.y + gf0;
        const float zg0 = e2.f.x + e3.f.x + gg0;
        const float zo0 = e2.f.y + e3.f.y + go0;
        const float zi1 = e4.f.x + e5.f.x + gi1;
        const float zf1 = e4.f.y + e5.f.y + gf1;
        const float zg1 = e6.f.x + e7.f.x + gg1;
        const float zo1 = e6.f.y + e7.f.y + go1;

        c0 = sigm(zf0) * c0 + sigm(zi0) * tanha(zg0);
        c1 = sigm(zf1) * c1 + sigm(zi1) * tanha(zg1);
        const float h_new0 = sigm(zo0) * tanha(c0);
        const float h_new1 = sigm(zo1) * tanha(c1);

        // Publish h slice (release via barrier.cluster.arrive)
        g_h[ra * 256 + n0 + np]       = h_new0;
        g_h[(ra + 1) * 256 + n0 + np] = h_new1;

        asm volatile("barrier.cluster.arrive.aligned;" ::: "memory");
        asm volatile("barrier.cluster.wait.aligned;" ::: "memory");

        // Rebuild full duplicated h image from g_h (cluster rows are contiguous)
        const float* src = g_h + row0 * 256;
        #pragma unroll
        for (int j = 0; j < 8; j++) {
            const float2 v = *(const float2*)(src + 2 * tid + 1024 * j);
            ((float4*)hs)[tid + 512 * j] = make_float4(v.x, v.x, v.y, v.y);
        }
        __syncthreads();
    }
    // g_h already holds the final h (written on the last step)
}

// ---------------------------------------------------------------------------
// K4: out = relu(h @ Wo + bo), [512,1]. One warp per batch row.
// ---------------------------------------------------------------------------
__global__ void out_kernel(const float* __restrict__ Wo,
                           const float* __restrict__ bo,
                           float* __restrict__ out)
{
    const int b = blockIdx.x;
    const int lane = threadIdx.x;
    float s = 0.f;
    #pragma unroll
    for (int k = lane; k < 256; k += 32) s += g_h[b*256 + k] * Wo[k];
    #pragma unroll
    for (int off = 16; off; off >>= 1) s += __shfl_down_sync(0xffffffffu, s, off);
    if (lane == 0) out[b] = fmaxf(s + bo[0], 0.f);
}

// ---------------------------------------------------------------------------
extern "C" void kernel_launch(void* const* d_in, const int* in_sizes, int n_in,
                              void* d_out, int out_size)
{
    const float* motion = (const float*)d_in[0];
    const float* robot  = (const float*)d_in[1];
    const float* osr    = (const float*)d_in[2];
    const float* osi    = (const float*)d_in[3];
    const float* hist   = (const float*)d_in[4];
    const float* act    = (const float*)d_in[5];
    const float* orr_   = (const float*)d_in[6];
    const float* ori_   = (const float*)d_in[7];
    const float* Wm  = (const float*)d_in[8];
    const float* bm  = (const float*)d_in[9];
    const float* Wr  = (const float*)d_in[10];
    const float* br  = (const float*)d_in[11];
    const float* Wre = (const float*)d_in[12];
    const float* bre = (const float*)d_in[13];
    const float* Wim = (const float*)d_in[14];
    const float* bim = (const float*)d_in[15];
    const float* Wc  = (const float*)d_in[16];
    const float* bc  = (const float*)d_in[17];
    const float* Wk  = (const float*)d_in[18];
    const float* Wrk = (const float*)d_in[19];
    const float* bl  = (const float*)d_in[20];
    const float* Wo  = (const float*)d_in[21];
    const float* bo  = (const float*)d_in[22];
    float* out = (float*)d_out;

    static int smem_set = 0;
    if (!smem_set) {
        cudaFuncSetAttribute(recur_cluster_kernel,
                             cudaFuncAttributeMaxDynamicSharedMemorySize, RSMEM);
        smem_set = 1;
    }

    reformat_wrk<<<256, 256>>>(Wrk);

    preamble_kernel<<<BATCH, 256>>>(motion, robot, osr, osi, orr_, ori_,
                                    Wm, bm, Wr, br, Wre, bre, Wim, bim, Wc, bc);

    dim3 g2(G4 / 128, (TSTEPS * BATCH) / 128);   // (8, 1020)
    xwk_kernel<<<g2, 256>>>(hist, act, Wk, bl);

    recur_cluster_kernel<<<NCLUST * CLSZ, RTHREADS, RSMEM>>>();

    out_kernel<<<BATCH, 32>>>(Wo, bo, out);
}

// round 5
// speedup vs baseline: 1.4812x; 1.4812x over previous
#include <cuda_runtime.h>
#include <math.h>
#include <stdint.h>

#define BATCH   512
#define STEPS   128
#define TSTEPS  255          // 127 history + 128 action
#define DIN     256
#define UDIM    256
#define G4      1024         // 4*UDIM

// Recurrence geometry
#define RROWS   6
#define RCTAS   ((BATCH + RROWS - 1) / RROWS)   // 86
#define RTH     256          // threads (one per gate feature)
#define NST     5            // cp.async ring stages
#define KSTG    8            // k-rows per stage
#define SS_STEP (UDIM / KSTG)                   // 32 stages per timestep
#define WS_F4   (NST * KSTG * 256)              // ring float4 count
#define RSMEM   (WS_F4 * 16 + RROWS * 256 * 8)  // 163840 + 12288 = 176128

// Scratch (static device allocations — no cudaMalloc anywhere)
__device__ float  g_state[BATCH * UDIM];
__device__ float  g_h[BATCH * UDIM];
__device__ float  g_G[(size_t)TSTEPS * BATCH * G4];   // 535 MB: x@Wk + bl, [t][b][4U]
__device__ float4 g_W4[256 * 256];                    // Wrk: (wi,wf,wg,wo) per (k,n)

// ---------------------------------------------------------------------------
// f32x2 packed-FMA helpers (sm_103a FFMA2 — only reachable via PTX)
// ---------------------------------------------------------------------------
union F2U { float2 f; unsigned long long u; };
union F4U { float4 f; ulonglong2 u; };

__device__ __forceinline__ void fma2(unsigned long long& d,
                                     unsigned long long a,
                                     unsigned long long b)
{
    asm("fma.rn.f32x2 %0, %1, %2, %0;" : "+l"(d) : "l"(a), "l"(b));
}
__device__ __forceinline__ unsigned long long dup2(float x)
{
    F2U t; t.f = make_float2(x, x); return t.u;
}
__device__ __forceinline__ float tanha(float x)
{
    float y; asm("tanh.approx.f32 %0, %1;" : "=f"(y) : "f"(x)); return y;
}
__device__ __forceinline__ float sigm(float x)
{
    return fmaf(0.5f, tanha(0.5f * x), 0.5f);
}
__device__ __forceinline__ void cpa16(uint32_t dst, const void* src)
{
    asm volatile("cp.async.cg.shared.global [%0], [%1], 16;"
                 :: "r"(dst), "l"(src) : "memory");
}
__device__ __forceinline__ uint32_t smem_u32(const void* p)
{
    uint32_t a;
    asm("{ .reg .u64 t; cvta.to.shared.u64 t, %1; cvt.u32.u64 %0, t; }"
        : "=r"(a) : "l"(p));
    return a;
}

// ---------------------------------------------------------------------------
// K0: reformat Wrk [256,1024] -> W4[k][n] = (wi,wf,wg,wo)
// ---------------------------------------------------------------------------
__global__ void reformat_wrk(const float* __restrict__ Wrk)
{
    const int idx = blockIdx.x * 256 + threadIdx.x;   // 65536
    const int k = idx >> 8, n = idx & 255;
    const float* w = Wrk + k * G4 + n;
    g_W4[idx] = make_float4(w[0], w[256], w[512], w[768]);
}

// ---------------------------------------------------------------------------
// K1: preamble — ms/rs/re/im + combine -> state [512,256]
// ---------------------------------------------------------------------------
__global__ void __launch_bounds__(256) preamble_kernel(
    const float* __restrict__ motion, const float* __restrict__ robot,
    const float* __restrict__ osr,    const float* __restrict__ osi,
    const float* __restrict__ orr_,   const float* __restrict__ ori_,
    const float* __restrict__ Wm, const float* __restrict__ bm,
    const float* __restrict__ Wr, const float* __restrict__ br,
    const float* __restrict__ Wre, const float* __restrict__ bre,
    const float* __restrict__ Wim, const float* __restrict__ bim,
    const float* __restrict__ Wc,  const float* __restrict__ bc)
{
    __shared__ float comb[768];
    const int row = blockIdx.x;
    const int n   = threadIdx.x;

    float s = bm[n];
    #pragma unroll 8
    for (int k = 0; k < 64; k++) s += motion[row*64 + k] * Wm[k*256 + n];
    comb[n] = fmaxf(s, 0.f);

    s = br[n];
    #pragma unroll 8
    for (int k = 0; k < 128; k++) s += robot[row*128 + k] * Wr[k*256 + n];
    comb[256 + n] = fmaxf(s, 0.f);

    if (n < 128) {
        float s3 = bre[n];
        #pragma unroll 8
        for (int k = 0; k < 64; k++) s3 += osr [row*64 + k] * Wre[k*128 + n];
        #pragma unroll 8
        for (int k = 0; k < 64; k++) s3 += orr_[row*64 + k] * Wre[(64+k)*128 + n];
        comb[512 + n] = fmaxf(s3, 0.f);
    } else {
        const int m = n - 128;
        float s4 = bim[m];
        #pragma unroll 8
        for (int k = 0; k < 64; k++) s4 += osi [row*64 + k] * Wim[k*128 + m];
        #pragma unroll 8
        for (int k = 0; k < 64; k++) s4 += ori_[row*64 + k] * Wim[(64+k)*128 + m];
        comb[640 + m] = fmaxf(s4, 0.f);
    }
    __syncthreads();

    float s5 = bc[n];
    #pragma unroll 8
    for (int k = 0; k < 768; k++) s5 += comb[k] * Wc[k*256 + n];
    g_state[row*256 + n] = fmaxf(s5, 0.f);
}

// ---------------------------------------------------------------------------
// K2: G = x @ Wk + bl.  M=130560, K=256, N=1024.
// 128x128 tile, BK=16, 256 threads, 8x8 microtile, FFMA2, reg-prefetch.
// ---------------------------------------------------------------------------
__global__ void __launch_bounds__(256, 1) xwk_kernel(
    const float* __restrict__ hist, const float* __restrict__ act,
    const float* __restrict__ Wk,   const float* __restrict__ bl)
{
    __shared__ float As[16][132];
    __shared__ float Bs[16][128];

    const int tid = threadIdx.x;
    const int tx  = tid & 15, ty = tid >> 4;
    const int bm0 = blockIdx.y * 128;
    const int bn0 = blockIdx.x * 128;

    const int ra = tid >> 2;
    const int kc = (tid & 3) * 4;
    const int mA0 = bm0 + ra, mA1 = bm0 + ra + 64;
    const int tA0 = mA0 >> 9, bA0 = mA0 & 511;
    const int tA1 = mA1 >> 9, bA1 = mA1 & 511;
    const float* arow0 = (tA0 < 127)
        ? (hist + ((size_t)bA0 * STEPS + tA0) * DIN)
        : (act  + ((size_t)bA0 * STEPS + (tA0 - 127)) * DIN);
    const float* arow1 = (tA1 < 127)
        ? (hist + ((size_t)bA1 * STEPS + tA1) * DIN)
        : (act  + ((size_t)bA1 * STEPS + (tA1 - 127)) * DIN);

    const int kb = tid >> 4;
    const int nb = (tid & 15) * 4;
    const float* bsrc = Wk + (size_t)kb * G4 + bn0 + nb;

    unsigned long long acc[8][4];
    #pragma unroll
    for (int i = 0; i < 8; i++)
        #pragma unroll
        for (int j = 0; j < 4; j++) acc[i][j] = 0ull;

    float4 a0 = *(const float4*)(arow0 + kc);
    float4 a1 = *(const float4*)(arow1 + kc);
    float4 b0 = *(const float4*)(bsrc);
    float4 b1 = *(const float4*)(bsrc + 64);

    for (int k0 = 0; k0 < 256; k0 += 16) {
        __syncthreads();
        As[kc+0][ra] = a0.x; As[kc+1][ra] = a0.y; As[kc+2][ra] = a0.z; As[kc+3][ra] = a0.w;
        As[kc+0][ra+64] = a1.x; As[kc+1][ra+64] = a1.y; As[kc+2][ra+64] = a1.z; As[kc+3][ra+64] = a1.w;
        *(float4*)&Bs[kb][nb]      = b0;
        *(float4*)&Bs[kb][nb + 64] = b1;
        __syncthreads();

        if (k0 + 16 < 256) {
            a0 = *(const float4*)(arow0 + k0 + 16 + kc);
            a1 = *(const float4*)(arow1 + k0 + 16 + kc);
            b0 = *(const float4*)(bsrc + (size_t)(k0 + 16) * G4);
            b1 = *(const float4*)(bsrc + (size_t)(k0 + 16) * G4 + 64);
        }

        #pragma unroll
        for (int k = 0; k < 16; k++) {
            float4 av0 = *(const float4*)&As[k][ty*8];
            float4 av1 = *(const float4*)&As[k][ty*8 + 4];
            F4U bv0, bv1;
            bv0.f = *(const float4*)&Bs[k][tx*8];
            bv1.f = *(const float4*)&Bs[k][tx*8 + 4];
            unsigned long long bp[4] = { bv0.u.x, bv0.u.y, bv1.u.x, bv1.u.y };
            float afl[8] = { av0.x, av0.y, av0.z, av0.w, av1.x, av1.y, av1.z, av1.w };
            #pragma unroll
            for (int i = 0; i < 8; i++) {
                unsigned long long ad = dup2(afl[i]);
                #pragma unroll
                for (int j = 0; j < 4; j++) fma2(acc[i][j], ad, bp[j]);
            }
        }
    }

    float blv[8];
    #pragma unroll
    for (int j = 0; j < 8; j++) blv[j] = bl[bn0 + tx*8 + j];

    #pragma unroll
    for (int i = 0; i < 8; i++) {
        const int m = bm0 + ty*8 + i;
        float v[8];
        #pragma unroll
        for (int j = 0; j < 4; j++) {
            F2U e; e.u = acc[i][j];
            v[j*2]   = e.f.x + blv[j*2];
            v[j*2+1] = e.f.y + blv[j*2+1];
        }
        float* dst = g_G + (size_t)m * G4 + bn0 + tx*8;
        *(float4*)dst       = make_float4(v[0], v[1], v[2], v[3]);
        *(float4*)(dst + 4) = make_float4(v[4], v[5], v[6], v[7]);
    }
}

// ---------------------------------------------------------------------------
// K3: persistent LSTM recurrence. 86 CTAs x 6 rows, 256 threads (full K).
// W stream staged through smem via cp.async ring (5 x 8k x 32KB), prefetch
// depth 4 -> inner loop is LDS + FFMA2 only. No cross-CTA sync.
// ---------------------------------------------------------------------------
__global__ void __launch_bounds__(RTH, 1) recur_kernel()
{
    extern __shared__ char smem[];
    float4* ws = (float4*)smem;                         // ring [5][8][256]
    float2* hs = (float2*)(smem + WS_F4 * 16);          // [r][256] dup'd h

    const int tid = threadIdx.x;                        // gate feature
    const int r0  = blockIdx.x * RROWS;
    const uint32_t ws_b = smem_u32(ws);

    int gr[RROWS];
    #pragma unroll
    for (int r = 0; r < RROWS; r++) gr[r] = min(r0 + r, BATCH - 1);

    float c[RROWS];
    #pragma unroll
    for (int r = 0; r < RROWS; r++) {
        c[r] = g_state[gr[r] * 256 + tid];
        hs[r * 256 + tid] = make_float2(c[r], c[r]);
    }
    __syncthreads();

    // stage issue: stage ss covers k rows [(ss%32)*8, +8); slot = ss % 5
    int slot_i = 0;                                     // (issue counter) % NST
    int kblk_i = 0;                                     // (issue counter) % 32
    #pragma unroll 1
    for (int p = 0; p < NST - 1; p++) {                 // prologue: 4 stages
        const float4* src = g_W4 + kblk_i * (KSTG * 256) + tid;
        uint32_t dst = ws_b + (uint32_t)(slot_i * KSTG * 256 + tid) * 16u;
        #pragma unroll
        for (int j = 0; j < KSTG; j++) cpa16(dst + j * 256 * 16, src + j * 256);
        asm volatile("cp.async.commit_group;" ::: "memory");
        if (++slot_i == NST) slot_i = 0;
        if (++kblk_i == SS_STEP) kblk_i = 0;
    }

    int slot_c = 0;                                     // (consume counter) % NST
    float hn[RROWS];

    #pragma unroll 1
    for (int t = 0; t < TSTEPS; t++) {
        // G prefetch for this step (consumed at step end; long latency cover)
        float gz[RROWS][4];
        #pragma unroll
        for (int r = 0; r < RROWS; r++) {
            const float* Gp = g_G + ((size_t)t * BATCH + gr[r]) * G4 + tid;
            gz[r][0] = Gp[0];   gz[r][1] = Gp[256];
            gz[r][2] = Gp[512]; gz[r][3] = Gp[768];
        }

        unsigned long long aif[RROWS], ago[RROWS];
        #pragma unroll
        for (int r = 0; r < RROWS; r++) { aif[r] = 0ull; ago[r] = 0ull; }

        #pragma unroll 1
        for (int s = 0; s < SS_STEP; s++) {
            asm volatile("cp.async.wait_group 3;" ::: "memory");
            __syncthreads();    // stage visible to all; prev slot fully consumed

            // issue replacement stage (depth stays 4)
            {
                const float4* src = g_W4 + kblk_i * (KSTG * 256) + tid;
                uint32_t dst = ws_b + (uint32_t)(slot_i * KSTG * 256 + tid) * 16u;
                #pragma unroll
                for (int j = 0; j < KSTG; j++) cpa16(dst + j * 256 * 16, src + j * 256);
                asm volatile("cp.async.commit_group;" ::: "memory");
                if (++slot_i == NST) slot_i = 0;
                if (++kblk_i == SS_STEP) kblk_i = 0;
            }

            const float4* stg = ws + slot_c * (KSTG * 256);
            const int kg = s * KSTG;
            #pragma unroll
            for (int i = 0; i < KSTG / 2; i++) {
                F4U w0, w1;
                w0.f = stg[(2*i)   * 256 + tid];
                w1.f = stg[(2*i+1) * 256 + tid];
                #pragma unroll
                for (int r = 0; r < RROWS; r++) {
                    F4U hh; hh.f = *(const float4*)&hs[r * 256 + kg + 2*i];
                    fma2(aif[r], w0.u.x, hh.u.x);
                    fma2(ago[r], w0.u.y, hh.u.x);
                    fma2(aif[r], w1.u.x, hh.u.y);
                    fma2(ago[r], w1.u.y, hh.u.y);
                }
            }
            if (++slot_c == NST) slot_c = 0;
        }

        // gate math + h update
        #pragma unroll
        for (int r = 0; r < RROWS; r++) {
            F2U eif, ego; eif.u = aif[r]; ego.u = ago[r];
            const float zi = eif.f.x + gz[r][0];
            const float zf = eif.f.y + gz[r][1];
            const float zg = ego.f.x + gz[r][2];
            const float zo = ego.f.y + gz[r][3];
            c[r]  = sigm(zf) * c[r] + sigm(zi) * tanha(zg);
            hn[r] = sigm(zo) * tanha(c[r]);
        }
        __syncthreads();        // everyone done reading old hs
        #pragma unroll
        for (int r = 0; r < RROWS; r++) hs[r * 256 + tid] = make_float2(hn[r], hn[r]);
        // visibility: next iteration's wait+__syncthreads orders these writes
    }

    #pragma unroll
    for (int r = 0; r < RROWS; r++)
        if (r0 + r < BATCH) g_h[(r0 + r) * 256 + tid] = hn[r];
}

// ---------------------------------------------------------------------------
// K4: out = relu(h @ Wo + bo), [512,1]. One warp per batch row.
// ---------------------------------------------------------------------------
__global__ void out_kernel(const float* __restrict__ Wo,
                           const float* __restrict__ bo,
                           float* __restrict__ out)
{
    const int b = blockIdx.x;
    const int lane = threadIdx.x;
    float s = 0.f;
    #pragma unroll
    for (int k = lane; k < 256; k += 32) s += g_h[b*256 + k] * Wo[k];
    #pragma unroll
    for (int off = 16; off; off >>= 1) s += __shfl_down_sync(0xffffffffu, s, off);
    if (lane == 0) out[b] = fmaxf(s + bo[0], 0.f);
}

// ---------------------------------------------------------------------------
extern "C" void kernel_launch(void* const* d_in, const int* in_sizes, int n_in,
                              void* d_out, int out_size)
{
    const float* motion = (const float*)d_in[0];
    const float* robot  = (const float*)d_in[1];
    const float* osr    = (const float*)d_in[2];
    const float* osi    = (const float*)d_in[3];
    const float* hist   = (const float*)d_in[4];
    const float* act    = (const float*)d_in[5];
    const float* orr_   = (const float*)d_in[6];
    const float* ori_   = (const float*)d_in[7];
    const float* Wm  = (const float*)d_in[8];
    const float* bm  = (const float*)d_in[9];
    const float* Wr  = (const float*)d_in[10];
    const float* br  = (const float*)d_in[11];
    const float* Wre = (const float*)d_in[12];
    const float* bre = (const float*)d_in[13];
    const float* Wim = (const float*)d_in[14];
    const float* bim = (const float*)d_in[15];
    const float* Wc  = (const float*)d_in[16];
    const float* bc  = (const float*)d_in[17];
    const float* Wk  = (const float*)d_in[18];
    const float* Wrk = (const float*)d_in[19];
    const float* bl  = (const float*)d_in[20];
    const float* Wo  = (const float*)d_in[21];
    const float* bo  = (const float*)d_in[22];
    float* out = (float*)d_out;

    static int smem_set = 0;
    if (!smem_set) {
        cudaFuncSetAttribute(recur_kernel,
                             cudaFuncAttributeMaxDynamicSharedMemorySize, RSMEM);
        smem_set = 1;
    }

    reformat_wrk<<<256, 256>>>(Wrk);

    preamble_kernel<<<BATCH, 256>>>(motion, robot, osr, osi, orr_, ori_,
                                    Wm, bm, Wr, br, Wre, bre, Wim, bim, Wc, bc);

    dim3 g2(G4 / 128, (TSTEPS * BATCH) / 128);   // (8, 1020)
    xwk_kernel<<<g2, 256>>>(hist, act, Wk, bl);

    recur_kernel<<<RCTAS, RTH, RSMEM>>>();

    out_kernel<<<BATCH, 32>>>(Wo, bo, out);
}